// round 3
// baseline (speedup 1.0000x reference)
#include <cuda_runtime.h>
#include <math.h>

#define Bb 16
#define Ss 256
#define Ee 256
#define ROWS (Bb*Ss)
#define FFNf 1024

__device__ float g_zx [ROWS*1024];
__device__ float g_wxp[256*1024];
__device__ float g_bth[1024];
__device__ float g_h  [ROWS*Ee];
__device__ float g_q  [ROWS*Ee];
__device__ float g_k  [ROWS*Ee];
__device__ float g_v  [ROWS*Ee];
__device__ float g_at [ROWS*Ee];
__device__ float g_ffq[ROWS*Ee];
__device__ float g_t1 [ROWS*FFNf];
__device__ float g_t2 [ROWS*Ee];

// pack Wx -> [k][g*256+j]; fold b+theta
__global__ void pack_kernel(const float* __restrict__ W, const float* __restrict__ B,
                            const float* __restrict__ Th) {
    int idx = blockIdx.x * 256 + threadIdx.x;
    int k = idx >> 10, n = idx & 1023, g = n >> 8, j = n & 255;
    g_wxp[idx] = W[g * 131072 + k * 256 + j];
    if (idx < 1024) g_bth[idx] = B[idx] + Th[idx];
}

// fp32 GEMM 64x64 tile, 256 thr, 4x4 micro. Optional embedding gather + ReLU.
template<bool GATHER, bool RELU>
__global__ __launch_bounds__(256) void gemm64_kernel(
    const float* __restrict__ A, const float* __restrict__ Bm, float* __restrict__ C,
    int M, int N, int K, const float* __restrict__ bias,
    const int* __restrict__ tok, const float* __restrict__ emb)
{
    __shared__ float AsT[16][68];
    __shared__ float Bs [16][68];
    __shared__ int   toks[64];
    const int t = threadIdx.x, tx = t & 15, ty = t >> 4;
    const int n0 = blockIdx.x << 6, m0 = blockIdx.y << 6;
    const int ar = t >> 2, ac4 = (t & 3) << 2;
    const int bkk = t >> 4, bn4 = (t & 15) << 2;
    if (GATHER) { if (t < 64) toks[t] = tok[m0 + t]; }
    __syncthreads();
    float acc[4][4];
#pragma unroll
    for (int i = 0; i < 4; i++)
#pragma unroll
        for (int j = 0; j < 4; j++) acc[i][j] = 0.f;
    const float* arow = GATHER ? (emb + (size_t)toks[ar] * K)
                               : (A   + (size_t)(m0 + ar) * K);
    for (int k0 = 0; k0 < K; k0 += 16) {
        float4 av = *(const float4*)(arow + k0 + ac4);
        float4 bv = *(const float4*)(Bm + (size_t)(k0 + bkk) * N + n0 + bn4);
        __syncthreads();
        AsT[ac4+0][ar] = av.x; AsT[ac4+1][ar] = av.y;
        AsT[ac4+2][ar] = av.z; AsT[ac4+3][ar] = av.w;
        *(float4*)(&Bs[bkk][bn4]) = bv;
        __syncthreads();
#pragma unroll
        for (int kk = 0; kk < 16; kk++) {
            float a[4], b[4];
            *(float4*)a = *(const float4*)(&AsT[kk][ty << 2]);
            *(float4*)b = *(const float4*)(&Bs [kk][tx << 2]);
#pragma unroll
            for (int i = 0; i < 4; i++)
#pragma unroll
                for (int j = 0; j < 4; j++) acc[i][j] = fmaf(a[i], b[j], acc[i][j]);
        }
    }
    float bb[4];
    *(float4*)bb = *(const float4*)(bias + n0 + (tx << 2));
#pragma unroll
    for (int i = 0; i < 4; i++) {
        float4 ov;
        ov.x = acc[i][0]+bb[0]; ov.y = acc[i][1]+bb[1];
        ov.z = acc[i][2]+bb[2]; ov.w = acc[i][3]+bb[3];
        if (RELU) { ov.x=fmaxf(ov.x,0.f); ov.y=fmaxf(ov.y,0.f);
                    ov.z=fmaxf(ov.z,0.f); ov.w=fmaxf(ov.w,0.f); }
        *(float4*)(C + (size_t)(m0 + (ty << 2) + i) * N + n0 + (tx << 2)) = ov;
    }
}

// QLSTM recurrence: one CTA (1024 thr) per batch element; only hx@Wh in loop
__global__ __launch_bounds__(1024) void lstm_kernel(const float* __restrict__ W,
                                                    float* __restrict__ hseq)
{
    __shared__ float hx[256], cx[256];
    __shared__ float red[4][1028];
    __shared__ float qv[1024];
    __shared__ float wtot[32];
    const int t = threadIdx.x, b = blockIdx.x;
    const int ks = t & 3, jj = (t >> 2) & 63, g = t >> 8;
    const int lane = t & 31, w = t >> 5;
    const float* wbase = W + g * 131072 + 65536 + ks * 256 + (jj << 2);
    if (t < 256) { hx[t] = 0.f; cx[t] = 0.f; }
    __syncthreads();
    const float* zxrow = g_zx + (size_t)b * 256 * 1024;
    for (int step = 0; step < 256; ++step) {
        float a0=0.f, a1=0.f, a2=0.f, a3=0.f;
        const float* wp = wbase;
#pragma unroll 8
        for (int kk = 0; kk < 64; ++kk) {
            float  hv = hx[(kk << 2) + ks];
            float4 wv = *(const float4*)wp;
            a0 = fmaf(hv, wv.x, a0); a1 = fmaf(hv, wv.y, a1);
            a2 = fmaf(hv, wv.z, a2); a3 = fmaf(hv, wv.w, a3);
            wp += 1024;
        }
        *(float4*)(&red[ks][(g << 8) + (jj << 2)]) = make_float4(a0, a1, a2, a3);
        __syncthreads();
        float z = red[0][t] + red[1][t] + red[2][t] + red[3][t]
                + zxrow[(size_t)step * 1024 + t];
        float p = cosf(z);
#pragma unroll
        for (int off = 1; off < 32; off <<= 1) {
            float u = __shfl_up_sync(0xffffffffu, p, off);
            if (lane >= off) p *= u;
        }
        if (lane == 31) wtot[w] = p;
        __syncthreads();
        float pre = 1.f;
        for (int ww = (g << 3); ww < w; ++ww) pre *= wtot[ww];
        qv[t] = p * pre;
        __syncthreads();
        if (t < 256) {
            float qf = qv[t], qi = qv[256+t], qg = qv[512+t], qo = qv[768+t];
            float f  = 1.f / (1.f + expf(-qf));
            float ii = 1.f / (1.f + expf(-qi));
            float gg = tanhf(qg);
            float oo = 1.f / (1.f + expf(-qo));
            float cn = f * cx[t] + ii * gg;
            cx[t] = cn;
            float hn = oo * tanhf(cn);
            hx[t] = hn;
            hseq[((size_t)b * 256 + step) * 256 + t] = hn;
        }
        __syncthreads();
    }
}

__global__ void add_pe_kernel(float* __restrict__ h) {
    int row = blockIdx.x, j = threadIdx.x, s = row & 255;
    float div = expf((float)((j >> 1) << 1) * (-9.210340371976184f / 256.f));
    float ang = (float)s * div;
    h[(size_t)row * 256 + j] += (j & 1) ? cosf(ang) : sinf(ang);
}

// cumprod(cos(h+theta)) per 256-row; one warp per row, 8 elems/lane
__global__ void qproj_kernel(const float* __restrict__ h, const float* __restrict__ th,
                             float* __restrict__ out) {
    const int w = threadIdx.x >> 5, lane = threadIdx.x & 31;
    const int row = blockIdx.x * 8 + w;
    const float* hr = h + (size_t)row * 256 + lane * 8;
    const float* tr = th + lane * 8;
    float4 h0 = *(const float4*)hr, h1 = *(const float4*)(hr + 4);
    float4 t0 = *(const float4*)tr, t1 = *(const float4*)(tr + 4);
    float p[8], run;
    run  = cosf(h0.x+t0.x); p[0]=run;  run *= cosf(h0.y+t0.y); p[1]=run;
    run *= cosf(h0.z+t0.z); p[2]=run;  run *= cosf(h0.w+t0.w); p[3]=run;
    run *= cosf(h1.x+t1.x); p[4]=run;  run *= cosf(h1.y+t1.y); p[5]=run;
    run *= cosf(h1.z+t1.z); p[6]=run;  run *= cosf(h1.w+t1.w); p[7]=run;
    float incl = run;
#pragma unroll
    for (int off = 1; off < 32; off <<= 1) {
        float u = __shfl_up_sync(0xffffffffu, incl, off);
        if (lane >= off) incl *= u;
    }
    float ex = __shfl_up_sync(0xffffffffu, incl, 1);
    if (lane == 0) ex = 1.f;
    float* o = out + (size_t)row * 256 + lane * 8;
    *(float4*)o     = make_float4(ex*p[0], ex*p[1], ex*p[2], ex*p[3]);
    *(float4*)(o+4) = make_float4(ex*p[4], ex*p[5], ex*p[6], ex*p[7]);
}

// fused attention: one CTA per (b,head); K and V^T staged in smem
__global__ __launch_bounds__(256) void attn_kernel(const float* __restrict__ Q,
    const float* __restrict__ K, const float* __restrict__ V, float* __restrict__ O)
{
    extern __shared__ float sm[];
    float* kh = sm;               // [256][36]
    float* vt = sm + 256 * 36;    // [32][260]
    float* ps = vt + 32 * 260;    // [8][256]
    float* qs = ps + 8 * 256;     // [8][32]
    const int b = blockIdx.x >> 3, hh = blockIdx.x & 7;
    const int t = threadIdx.x, w = t >> 5, lane = t & 31;
    const size_t base = ((size_t)b * 256) * 256 + hh * 32;
    for (int idx = t; idx < 8192; idx += 256) {
        int kr = idx >> 5, d = idx & 31;
        size_t go = base + (size_t)kr * 256 + d;
        kh[kr * 36 + d]  = K[go];
        vt[d * 260 + kr] = V[go];
    }
    __syncthreads();
    float* qsw = qs + w * 32;
    float* psw = ps + w * 256;
    for (int r = w; r < 256; r += 8) {
        qsw[lane] = Q[base + (size_t)r * 256 + lane];
        __syncwarp();
        float s[8];
#pragma unroll
        for (int c = 0; c < 8; c++) {
            const float* kr = kh + (c * 32 + lane) * 36;
            float acc = 0.f;
#pragma unroll
            for (int d4 = 0; d4 < 8; d4++) {
                float4 kv = *(const float4*)(kr + (d4 << 2));
                float4 qv = *(const float4*)(qsw + (d4 << 2));
                acc = fmaf(kv.x,qv.x,acc); acc = fmaf(kv.y,qv.y,acc);
                acc = fmaf(kv.z,qv.z,acc); acc = fmaf(kv.w,qv.w,acc);
            }
            s[c] = acc * 0.17677669529663689f;
        }
        float m = s[0];
#pragma unroll
        for (int c = 1; c < 8; c++) m = fmaxf(m, s[c]);
#pragma unroll
        for (int off = 16; off; off >>= 1) m = fmaxf(m, __shfl_xor_sync(0xffffffffu, m, off));
        float sum = 0.f;
#pragma unroll
        for (int c = 0; c < 8; c++) { s[c] = __expf(s[c] - m); sum += s[c]; }
#pragma unroll
        for (int off = 16; off; off >>= 1) sum += __shfl_xor_sync(0xffffffffu, sum, off);
#pragma unroll
        for (int c = 0; c < 8; c++) psw[c * 32 + lane] = s[c];
        __syncwarp();
        float acc = 0.f;
        const float* vr = vt + lane * 260;
#pragma unroll
        for (int k4 = 0; k4 < 64; k4++) {
            float4 pv = *(const float4*)(psw + (k4 << 2));
            float4 vv = *(const float4*)(vr  + (k4 << 2));
            acc = fmaf(pv.x,vv.x,acc); acc = fmaf(pv.y,vv.y,acc);
            acc = fmaf(pv.z,vv.z,acc); acc = fmaf(pv.w,vv.w,acc);
        }
        O[base + (size_t)r * 256 + lane] = acc / sum;
        __syncwarp();
    }
}

__global__ void resid_ln_kernel(float* __restrict__ h, const float* __restrict__ d,
                                const float* __restrict__ gw, const float* __restrict__ bw) {
    const int row = blockIdx.x, j = threadIdx.x, w = j >> 5, lane = j & 31;
    __shared__ float ssum[8], ssq[8];
    size_t off = (size_t)row * 256 + j;
    float v = h[off] + d[off];
    float s = v, s2 = v * v;
#pragma unroll
    for (int o = 16; o; o >>= 1) {
        s  += __shfl_xor_sync(0xffffffffu, s, o);
        s2 += __shfl_xor_sync(0xffffffffu, s2, o);
    }
    if (lane == 0) { ssum[w] = s; ssq[w] = s2; }
    __syncthreads();
    if (j == 0) {
        float S = 0.f, S2 = 0.f;
        for (int i = 0; i < 8; i++) { S += ssum[i]; S2 += ssq[i]; }
        ssum[0] = S; ssq[0] = S2;
    }
    __syncthreads();
    float mean = ssum[0] * (1.f/256.f);
    float var  = ssq[0]  * (1.f/256.f) - mean * mean;
    h[off] = (v - mean) * rsqrtf(var + 1e-5f) * gw[j] + bw[j];
}

__global__ void pool_cls_kernel(const float* __restrict__ h, const float* __restrict__ Wc,
                                const float* __restrict__ bc, float* __restrict__ out) {
    __shared__ float pooled[256];
    const int b = blockIdx.x, e = threadIdx.x;
    float s = 0.f;
    for (int tt = 0; tt < 256; ++tt) s += h[((size_t)b * 256 + tt) * 256 + e];
    pooled[e] = s * (1.f/256.f);
    __syncthreads();
    if (e < 4) {
        float a = bc[e];
        for (int i = 0; i < 256; i++) a = fmaf(pooled[i], Wc[i * 4 + e], a);
        out[b * 4 + e] = a;
    }
}

extern "C" void kernel_launch(void* const* d_in, const int* in_sizes, int n_in,
                              void* d_out, int out_size)
{
    const int*   x      = (const int*)  d_in[0];
    const float* tokemb = (const float*)d_in[1];
    const float* lstmW  = (const float*)d_in[2];
    const float* lstmB  = (const float*)d_in[3];
    const float* lstmTh = (const float*)d_in[4];
    const float* ln1g   = (const float*)d_in[5];
    const float* ln1b   = (const float*)d_in[6];
    const float* ln2g   = (const float*)d_in[7];
    const float* ln2b   = (const float*)d_in[8];
    const float* qkvTh  = (const float*)d_in[9];
    const float* combW  = (const float*)d_in[10];
    const float* combB  = (const float*)d_in[11];
    const float* ffnTh  = (const float*)d_in[12];
    const float* lin1W  = (const float*)d_in[13];
    const float* lin1B  = (const float*)d_in[14];
    const float* lin2W  = (const float*)d_in[15];
    const float* lin2B  = (const float*)d_in[16];
    const float* clsW   = (const float*)d_in[17];
    const float* clsB   = (const float*)d_in[18];
    float* out = (float*)d_out;

    float *p_zx,*p_wxp,*p_bth,*p_h,*p_q,*p_k,*p_v,*p_at,*p_ffq,*p_t1,*p_t2;
    cudaGetSymbolAddress((void**)&p_zx,  g_zx);
    cudaGetSymbolAddress((void**)&p_wxp, g_wxp);
    cudaGetSymbolAddress((void**)&p_bth, g_bth);
    cudaGetSymbolAddress((void**)&p_h,   g_h);
    cudaGetSymbolAddress((void**)&p_q,   g_q);
    cudaGetSymbolAddress((void**)&p_k,   g_k);
    cudaGetSymbolAddress((void**)&p_v,   g_v);
    cudaGetSymbolAddress((void**)&p_at,  g_at);
    cudaGetSymbolAddress((void**)&p_ffq, g_ffq);
    cudaGetSymbolAddress((void**)&p_t1,  g_t1);
    cudaGetSymbolAddress((void**)&p_t2,  g_t2);

    cudaFuncSetAttribute(attn_kernel, cudaFuncAttributeMaxDynamicSharedMemorySize, 79360);

    pack_kernel<<<1024, 256>>>(lstmW, lstmB, lstmTh);
    gemm64_kernel<true, false><<<dim3(16, 64), 256>>>(
        nullptr, p_wxp, p_zx, ROWS, 1024, 256, p_bth, x, tokemb);
    lstm_kernel<<<Bb, 1024>>>(lstmW, p_h);
    add_pe_kernel<<<ROWS, 256>>>(p_h);

    for (int l = 0; l < 2; l++) {
        qproj_kernel<<<ROWS/8, 256>>>(p_h, qkvTh + (l*3+0)*256, p_q);
        qproj_kernel<<<ROWS/8, 256>>>(p_h, qkvTh + (l*3+1)*256, p_k);
        qproj_kernel<<<ROWS/8, 256>>>(p_h, qkvTh + (l*3+2)*256, p_v);
        attn_kernel<<<Bb*8, 256, 79360>>>(p_q, p_k, p_v, p_at);
        gemm64_kernel<false, false><<<dim3(4, 64), 256>>>(
            p_at, combW + l*256*256, p_t2, ROWS, 256, 256,
            combB + l*256, nullptr, nullptr);
        resid_ln_kernel<<<ROWS, 256>>>(p_h, p_t2, ln1g + l*256, ln1b + l*256);
        qproj_kernel<<<ROWS/8, 256>>>(p_h, ffnTh + l*256, p_ffq);
        gemm64_kernel<false, true><<<dim3(16, 64), 256>>>(
            p_ffq, lin1W + l*256*1024, p_t1, ROWS, 1024, 256,
            lin1B + l*1024, nullptr, nullptr);
        gemm64_kernel<false, false><<<dim3(4, 64), 256>>>(
            p_t1, lin2W + l*1024*256, p_t2, ROWS, 256, 1024,
            lin2B + l*256, nullptr, nullptr);
        resid_ln_kernel<<<ROWS, 256>>>(p_h, p_t2, ln2g + l*256, ln2b + l*256);
    }
    pool_cls_kernel<<<Bb, 256>>>(p_h, clsW, clsB, out);
}

// round 4
// speedup vs baseline: 3.1276x; 3.1276x over previous
#include <cuda_runtime.h>
#include <math.h>
#include <cooperative_groups.h>
namespace cg = cooperative_groups;

#define Bb 16
#define Ss 256
#define Ee 256
#define ROWS (Bb*Ss)
#define FFNf 1024

__device__ float g_zx [ROWS*1024];
__device__ float g_wxp[256*1024];
__device__ float g_bth[1024];
__device__ float g_h  [ROWS*Ee];
__device__ float g_q  [ROWS*Ee];
__device__ float g_k  [ROWS*Ee];
__device__ float g_v  [ROWS*Ee];
__device__ float g_at [ROWS*Ee];
__device__ float g_ffq[ROWS*Ee];
__device__ float g_t1 [ROWS*FFNf];
__device__ float g_t2 [ROWS*Ee];

__device__ __forceinline__ float sigm_f(float x) {
    return 1.f / (1.f + __expf(-x));
}
__device__ __forceinline__ float tanh_f(float x) {
    float t = __expf(-2.f * x);
    return (1.f - t) / (1.f + t);
}

// pack Wx -> [k][g*256+j]; fold b+theta
__global__ void pack_kernel(const float* __restrict__ W, const float* __restrict__ B,
                            const float* __restrict__ Th) {
    int idx = blockIdx.x * 256 + threadIdx.x;
    int k = idx >> 10, n = idx & 1023, g = n >> 8, j = n & 255;
    g_wxp[idx] = W[g * 131072 + k * 256 + j];
    if (idx < 1024) g_bth[idx] = B[idx] + Th[idx];
}

// fp32 GEMM 64x64 tile, 256 thr, 4x4 micro, prefetch-pipelined K tiles.
template<bool GATHER, bool RELU>
__global__ __launch_bounds__(256) void gemm64_kernel(
    const float* __restrict__ A, const float* __restrict__ Bm, float* __restrict__ C,
    int M, int N, int K, const float* __restrict__ bias,
    const int* __restrict__ tok, const float* __restrict__ emb)
{
    __shared__ float AsT[16][68];
    __shared__ float Bs [16][68];
    __shared__ int   toks[64];
    const int t = threadIdx.x, tx = t & 15, ty = t >> 4;
    const int n0 = blockIdx.x << 6, m0 = blockIdx.y << 6;
    const int ar = t >> 2, ac4 = (t & 3) << 2;
    const int bkk = t >> 4, bn4 = (t & 15) << 2;
    if (GATHER) { if (t < 64) toks[t] = tok[m0 + t]; __syncthreads(); }
    float acc[4][4];
#pragma unroll
    for (int i = 0; i < 4; i++)
#pragma unroll
        for (int j = 0; j < 4; j++) acc[i][j] = 0.f;
    const float* arow = GATHER ? (emb + (size_t)toks[ar] * K)
                               : (A   + (size_t)(m0 + ar) * K);
    float4 av = *(const float4*)(arow + ac4);
    float4 bv = *(const float4*)(Bm + (size_t)bkk * N + n0 + bn4);
    int k0 = 0;
    while (true) {
        __syncthreads();
        AsT[ac4+0][ar] = av.x; AsT[ac4+1][ar] = av.y;
        AsT[ac4+2][ar] = av.z; AsT[ac4+3][ar] = av.w;
        *(float4*)(&Bs[bkk][bn4]) = bv;
        __syncthreads();
        k0 += 16;
        bool more = (k0 < K);
        if (more) {   // prefetch next tile while computing this one
            av = *(const float4*)(arow + k0 + ac4);
            bv = *(const float4*)(Bm + (size_t)(k0 + bkk) * N + n0 + bn4);
        }
#pragma unroll
        for (int kk = 0; kk < 16; kk++) {
            float a[4], b[4];
            *(float4*)a = *(const float4*)(&AsT[kk][ty << 2]);
            *(float4*)b = *(const float4*)(&Bs [kk][tx << 2]);
#pragma unroll
            for (int i = 0; i < 4; i++)
#pragma unroll
                for (int j = 0; j < 4; j++) acc[i][j] = fmaf(a[i], b[j], acc[i][j]);
        }
        if (!more) break;
    }
    float bb[4];
    *(float4*)bb = *(const float4*)(bias + n0 + (tx << 2));
#pragma unroll
    for (int i = 0; i < 4; i++) {
        float4 ov;
        ov.x = acc[i][0]+bb[0]; ov.y = acc[i][1]+bb[1];
        ov.z = acc[i][2]+bb[2]; ov.w = acc[i][3]+bb[3];
        if (RELU) { ov.x=fmaxf(ov.x,0.f); ov.y=fmaxf(ov.y,0.f);
                    ov.z=fmaxf(ov.z,0.f); ov.w=fmaxf(ov.w,0.f); }
        *(float4*)(C + (size_t)(m0 + (ty << 2) + i) * N + n0 + (tx << 2)) = ov;
    }
}

// ---------------------------------------------------------------------------
// QLSTM recurrence, cluster version.
// 128 CTAs = 16 batches x 8 slices (gate g = rank>>1, half = rank&1).
// Each CTA owns 128 gate-columns; its 128KB W slice lives in SHARED memory,
// so the 256-step loop does zero global W traffic. Per step: smem dot,
// cumprod of local 128 cols, ONE cluster.sync, DSMEM gate exchange
// (cross-half prefix applied reader-side), replicated state update.
// ---------------------------------------------------------------------------
#define LSTM_SMEM_FLOATS (32768 + 8*132 + 2*132 + 256 + 256 + 8)
__global__ __cluster_dims__(8,1,1) __launch_bounds__(256)
void lstm_kernel(const float* __restrict__ W, float* __restrict__ hseq)
{
    extern __shared__ float sm[];
    float* Wsm     = sm;                       // [256][128]
    float* red     = sm + 32768;               // [8][132]
    float* scanbuf = red + 8*132;              // [2][132] (double buffer)
    float* hx      = scanbuf + 2*132;          // [256]
    float* cx      = hx + 256;                 // [256]
    float* wtot    = cx + 256;                 // [4..8]

    cg::cluster_group cluster = cg::this_cluster();
    const int rank = (int)cluster.block_rank();
    const int g    = rank >> 1, half = rank & 1;
    const int b    = blockIdx.x >> 3;
    const int t    = threadIdx.x;
    const int ks   = t >> 5, jc = t & 31;      // 8-way k split, 32 col-groups
    const int lane = t & 31, w = t >> 5;

    // preload W slice: rows k in [0,256), cols [g*256 + half*128, +128)
    const float* gW = W + g * 131072 + 65536 + half * 128;
    for (int i = t; i < 8192; i += 256) {
        int k = i >> 5, j4 = (i & 31) << 2;
        *(float4*)&Wsm[k * 128 + j4] = *(const float4*)(gW + (size_t)k * 256 + j4);
    }
    hx[t] = 0.f; cx[t] = 0.f;
    __syncthreads();

    // peer scanbuf pointers
    float* speer[8];
#pragma unroll
    for (int r = 0; r < 8; r++)
        speer[r] = (float*)cluster.map_shared_rank((void*)scanbuf, r);

    const float* zxp = g_zx + (size_t)b * 256 * 1024 + g * 256 + half * 128;

    for (int step = 0; step < 256; ++step) {
        const int par = step & 1;
        // ---- dot: z_partial[jc*4..+3] over k = ks + 8*kk ----
        float a0=0.f, a1=0.f, a2=0.f, a3=0.f;
        const float* wp = Wsm + ks * 128 + (jc << 2);
#pragma unroll 8
        for (int kk = 0; kk < 32; ++kk) {
            float  hv = hx[(kk << 3) + ks];
            float4 wv = *(const float4*)wp;
            a0 = fmaf(hv, wv.x, a0); a1 = fmaf(hv, wv.y, a1);
            a2 = fmaf(hv, wv.z, a2); a3 = fmaf(hv, wv.w, a3);
            wp += 8 * 128;
        }
        *(float4*)&red[ks * 132 + (jc << 2)] = make_float4(a0, a1, a2, a3);
        __syncthreads();
        // ---- z, cos, local inclusive cumprod over 128 cols ----
        float p = 0.f;
        if (t < 128) {
            float z = red[t] + red[132 + t] + red[264 + t] + red[396 + t]
                    + red[528 + t] + red[660 + t] + red[792 + t] + red[924 + t]
                    + zxp[(size_t)step * 1024 + t];
            p = __cosf(z);
#pragma unroll
            for (int off = 1; off < 32; off <<= 1) {
                float u = __shfl_up_sync(0xffffffffu, p, off);
                if (lane >= off) p *= u;
            }
            if (lane == 31) wtot[w] = p;
        }
        __syncthreads();
        if (t < 128) {
            float pre = 1.f;
            for (int ww = 0; ww < w; ++ww) pre *= wtot[ww];
            scanbuf[par * 132 + t] = p * pre;
        }
        cluster.sync();
        // ---- gate exchange + state update (replicated in every CTA) ----
        {
            const int sh = t >> 7, off = t & 127;
            float qg4[4];
#pragma unroll
            for (int gg = 0; gg < 4; gg++) {
                const float* lo = speer[gg * 2];
                const float* me = speer[gg * 2 + sh];
                float v = me[par * 132 + off];
                if (sh) v *= lo[par * 132 + 127];   // cross-half prefix
                qg4[gg] = v;
            }
            float f  = sigm_f(qg4[0]);
            float ii = sigm_f(qg4[1]);
            float gg = tanh_f(qg4[2]);
            float oo = sigm_f(qg4[3]);
            float cn = f * cx[t] + ii * gg;
            cx[t] = cn;
            float hn = oo * tanh_f(cn);
            hx[t] = hn;
            if (rank == 0)
                hseq[((size_t)b * 256 + step) * 256 + t] = hn;
        }
        __syncthreads();
    }
}

__global__ void add_pe_kernel(float* __restrict__ h) {
    int row = blockIdx.x, j = threadIdx.x, s = row & 255;
    float div = __expf((float)((j >> 1) << 1) * (-9.210340371976184f / 256.f));
    float ang = (float)s * div;
    h[(size_t)row * 256 + j] += (j & 1) ? __cosf(ang) : __sinf(ang);
}

// cumprod(cos(h+theta)) per 256-row; one warp per row, 8 elems/lane
__global__ void qproj_kernel(const float* __restrict__ h, const float* __restrict__ th,
                             float* __restrict__ out) {
    const int w = threadIdx.x >> 5, lane = threadIdx.x & 31;
    const int row = blockIdx.x * 8 + w;
    const float* hr = h + (size_t)row * 256 + lane * 8;
    const float* tr = th + lane * 8;
    float4 h0 = *(const float4*)hr, h1 = *(const float4*)(hr + 4);
    float4 t0 = *(const float4*)tr, t1 = *(const float4*)(tr + 4);
    float p[8], run;
    run  = __cosf(h0.x+t0.x); p[0]=run;  run *= __cosf(h0.y+t0.y); p[1]=run;
    run *= __cosf(h0.z+t0.z); p[2]=run;  run *= __cosf(h0.w+t0.w); p[3]=run;
    run *= __cosf(h1.x+t1.x); p[4]=run;  run *= __cosf(h1.y+t1.y); p[5]=run;
    run *= __cosf(h1.z+t1.z); p[6]=run;  run *= __cosf(h1.w+t1.w); p[7]=run;
    float incl = run;
#pragma unroll
    for (int off = 1; off < 32; off <<= 1) {
        float u = __shfl_up_sync(0xffffffffu, incl, off);
        if (lane >= off) incl *= u;
    }
    float ex = __shfl_up_sync(0xffffffffu, incl, 1);
    if (lane == 0) ex = 1.f;
    float* o = out + (size_t)row * 256 + lane * 8;
    *(float4*)o     = make_float4(ex*p[0], ex*p[1], ex*p[2], ex*p[3]);
    *(float4*)(o+4) = make_float4(ex*p[4], ex*p[5], ex*p[6], ex*p[7]);
}

// fused attention: one CTA per (b,head); K and V^T staged in smem
__global__ __launch_bounds__(256) void attn_kernel(const float* __restrict__ Q,
    const float* __restrict__ K, const float* __restrict__ V, float* __restrict__ O)
{
    extern __shared__ float sm[];
    float* kh = sm;               // [256][36]
    float* vt = sm + 256 * 36;    // [32][260]
    float* ps = vt + 32 * 260;    // [8][256]
    float* qs = ps + 8 * 256;     // [8][32]
    const int b = blockIdx.x >> 3, hh = blockIdx.x & 7;
    const int t = threadIdx.x, w = t >> 5, lane = t & 31;
    const size_t base = ((size_t)b * 256) * 256 + hh * 32;
    for (int idx = t; idx < 8192; idx += 256) {
        int kr = idx >> 5, d = idx & 31;
        size_t go = base + (size_t)kr * 256 + d;
        kh[kr * 36 + d]  = K[go];
        vt[d * 260 + kr] = V[go];
    }
    __syncthreads();
    float* qsw = qs + w * 32;
    float* psw = ps + w * 256;
    for (int r = w; r < 256; r += 8) {
        qsw[lane] = Q[base + (size_t)r * 256 + lane];
        __syncwarp();
        float s[8];
#pragma unroll
        for (int c = 0; c < 8; c++) {
            const float* kr = kh + (c * 32 + lane) * 36;
            float acc = 0.f;
#pragma unroll
            for (int d4 = 0; d4 < 8; d4++) {
                float4 kv = *(const float4*)(kr + (d4 << 2));
                float4 qv = *(const float4*)(qsw + (d4 << 2));
                acc = fmaf(kv.x,qv.x,acc); acc = fmaf(kv.y,qv.y,acc);
                acc = fmaf(kv.z,qv.z,acc); acc = fmaf(kv.w,qv.w,acc);
            }
            s[c] = acc * 0.17677669529663689f;
        }
        float m = s[0];
#pragma unroll
        for (int c = 1; c < 8; c++) m = fmaxf(m, s[c]);
#pragma unroll
        for (int off = 16; off; off >>= 1) m = fmaxf(m, __shfl_xor_sync(0xffffffffu, m, off));
        float sum = 0.f;
#pragma unroll
        for (int c = 0; c < 8; c++) { s[c] = __expf(s[c] - m); sum += s[c]; }
#pragma unroll
        for (int off = 16; off; off >>= 1) sum += __shfl_xor_sync(0xffffffffu, sum, off);
#pragma unroll
        for (int c = 0; c < 8; c++) psw[c * 32 + lane] = s[c];
        __syncwarp();
        float acc = 0.f;
        const float* vr = vt + lane * 260;
#pragma unroll
        for (int k4 = 0; k4 < 64; k4++) {
            float4 pv = *(const float4*)(psw + (k4 << 2));
            float4 vv = *(const float4*)(vr  + (k4 << 2));
            acc = fmaf(pv.x,vv.x,acc); acc = fmaf(pv.y,vv.y,acc);
            acc = fmaf(pv.z,vv.z,acc); acc = fmaf(pv.w,vv.w,acc);
        }
        O[base + (size_t)r * 256 + lane] = acc / sum;
        __syncwarp();
    }
}

__global__ void resid_ln_kernel(float* __restrict__ h, const float* __restrict__ d,
                                const float* __restrict__ gw, const float* __restrict__ bw) {
    const int row = blockIdx.x, j = threadIdx.x, w = j >> 5, lane = j & 31;
    __shared__ float ssum[8], ssq[8];
    size_t off = (size_t)row * 256 + j;
    float v = h[off] + d[off];
    float s = v, s2 = v * v;
#pragma unroll
    for (int o = 16; o; o >>= 1) {
        s  += __shfl_xor_sync(0xffffffffu, s, o);
        s2 += __shfl_xor_sync(0xffffffffu, s2, o);
    }
    if (lane == 0) { ssum[w] = s; ssq[w] = s2; }
    __syncthreads();
    if (j == 0) {
        float S = 0.f, S2 = 0.f;
        for (int i = 0; i < 8; i++) { S += ssum[i]; S2 += ssq[i]; }
        ssum[0] = S; ssq[0] = S2;
    }
    __syncthreads();
    float mean = ssum[0] * (1.f/256.f);
    float var  = ssq[0]  * (1.f/256.f) - mean * mean;
    h[off] = (v - mean) * rsqrtf(var + 1e-5f) * gw[j] + bw[j];
}

__global__ void pool_cls_kernel(const float* __restrict__ h, const float* __restrict__ Wc,
                                const float* __restrict__ bc, float* __restrict__ out) {
    __shared__ float pooled[256];
    const int b = blockIdx.x, e = threadIdx.x;
    float s = 0.f;
    for (int tt = 0; tt < 256; ++tt) s += h[((size_t)b * 256 + tt) * 256 + e];
    pooled[e] = s * (1.f/256.f);
    __syncthreads();
    if (e < 4) {
        float a = bc[e];
        for (int i = 0; i < 256; i++) a = fmaf(pooled[i], Wc[i * 4 + e], a);
        out[b * 4 + e] = a;
    }
}

extern "C" void kernel_launch(void* const* d_in, const int* in_sizes, int n_in,
                              void* d_out, int out_size)
{
    const int*   x      = (const int*)  d_in[0];
    const float* tokemb = (const float*)d_in[1];
    const float* lstmW  = (const float*)d_in[2];
    const float* lstmB  = (const float*)d_in[3];
    const float* lstmTh = (const float*)d_in[4];
    const float* ln1g   = (const float*)d_in[5];
    const float* ln1b   = (const float*)d_in[6];
    const float* ln2g   = (const float*)d_in[7];
    const float* ln2b   = (const float*)d_in[8];
    const float* qkvTh  = (const float*)d_in[9];
    const float* combW  = (const float*)d_in[10];
    const float* combB  = (const float*)d_in[11];
    const float* ffnTh  = (const float*)d_in[12];
    const float* lin1W  = (const float*)d_in[13];
    const float* lin1B  = (const float*)d_in[14];
    const float* lin2W  = (const float*)d_in[15];
    const float* lin2B  = (const float*)d_in[16];
    const float* clsW   = (const float*)d_in[17];
    const float* clsB   = (const float*)d_in[18];
    float* out = (float*)d_out;

    float *p_zx,*p_wxp,*p_bth,*p_h,*p_q,*p_k,*p_v,*p_at,*p_ffq,*p_t1,*p_t2;
    cudaGetSymbolAddress((void**)&p_zx,  g_zx);
    cudaGetSymbolAddress((void**)&p_wxp, g_wxp);
    cudaGetSymbolAddress((void**)&p_bth, g_bth);
    cudaGetSymbolAddress((void**)&p_h,   g_h);
    cudaGetSymbolAddress((void**)&p_q,   g_q);
    cudaGetSymbolAddress((void**)&p_k,   g_k);
    cudaGetSymbolAddress((void**)&p_v,   g_v);
    cudaGetSymbolAddress((void**)&p_at,  g_at);
    cudaGetSymbolAddress((void**)&p_ffq, g_ffq);
    cudaGetSymbolAddress((void**)&p_t1,  g_t1);
    cudaGetSymbolAddress((void**)&p_t2,  g_t2);

    cudaFuncSetAttribute(attn_kernel, cudaFuncAttributeMaxDynamicSharedMemorySize, 79360);
    cudaFuncSetAttribute(lstm_kernel, cudaFuncAttributeMaxDynamicSharedMemorySize,
                         LSTM_SMEM_FLOATS * 4);

    pack_kernel<<<1024, 256>>>(lstmW, lstmB, lstmTh);
    gemm64_kernel<true, false><<<dim3(16, 64), 256>>>(
        nullptr, p_wxp, p_zx, ROWS, 1024, 256, p_bth, x, tokemb);
    lstm_kernel<<<128, 256, LSTM_SMEM_FLOATS * 4>>>(lstmW, p_h);
    add_pe_kernel<<<ROWS, 256>>>(p_h);

    for (int l = 0; l < 2; l++) {
        qproj_kernel<<<ROWS/8, 256>>>(p_h, qkvTh + (l*3+0)*256, p_q);
        qproj_kernel<<<ROWS/8, 256>>>(p_h, qkvTh + (l*3+1)*256, p_k);
        qproj_kernel<<<ROWS/8, 256>>>(p_h, qkvTh + (l*3+2)*256, p_v);
        attn_kernel<<<Bb*8, 256, 79360>>>(p_q, p_k, p_v, p_at);
        gemm64_kernel<false, false><<<dim3(4, 64), 256>>>(
            p_at, combW + l*256*256, p_t2, ROWS, 256, 256,
            combB + l*256, nullptr, nullptr);
        resid_ln_kernel<<<ROWS, 256>>>(p_h, p_t2, ln1g + l*256, ln1b + l*256);
        qproj_kernel<<<ROWS/8, 256>>>(p_h, ffnTh + l*256, p_ffq);
        gemm64_kernel<false, true><<<dim3(16, 64), 256>>>(
            p_ffq, lin1W + l*256*1024, p_t1, ROWS, 1024, 256,
            lin1B + l*1024, nullptr, nullptr);
        gemm64_kernel<false, false><<<dim3(4, 64), 256>>>(
            p_t1, lin2W + l*1024*256, p_t2, ROWS, 256, 1024,
            lin2B + l*256, nullptr, nullptr);
        resid_ln_kernel<<<ROWS, 256>>>(p_h, p_t2, ln2g + l*256, ln2b + l*256);
    }
    pool_cls_kernel<<<Bb, 256>>>(p_h, clsW, clsB, out);
}

// round 5
// speedup vs baseline: 3.3553x; 1.0728x over previous
#include <cuda_runtime.h>
#include <math.h>
#include <cooperative_groups.h>
namespace cg = cooperative_groups;

#define Bb 16
#define Ss 256
#define Ee 256
#define ROWS (Bb*Ss)
#define FFNf 1024

__device__ float g_zx [ROWS*1024];
__device__ float g_wxp[256*1024];
__device__ float g_bth[1024];
__device__ float g_h  [ROWS*Ee];
__device__ float g_q  [ROWS*Ee];
__device__ float g_k  [ROWS*Ee];
__device__ float g_v  [ROWS*Ee];
__device__ float g_at [ROWS*Ee];
__device__ float g_ffq[ROWS*Ee];
__device__ float g_t1 [ROWS*FFNf];
__device__ float g_t2 [ROWS*Ee];

__device__ __forceinline__ float sigm_f(float x) { return 1.f / (1.f + __expf(-x)); }
__device__ __forceinline__ float tanh_f(float x) {
    float t = __expf(-2.f * x);
    return (1.f - t) / (1.f + t);
}

// pack Wx -> [k][g*256+j]; fold b+theta
__global__ void pack_kernel(const float* __restrict__ W, const float* __restrict__ B,
                            const float* __restrict__ Th) {
    int idx = blockIdx.x * 256 + threadIdx.x;
    int k = idx >> 10, n = idx & 1023, g = n >> 8, j = n & 255;
    g_wxp[idx] = W[g * 131072 + k * 256 + j];
    if (idx < 1024) g_bth[idx] = B[idx] + Th[idx];
}

// -------- fp32 GEMM: 128x64 tile, 256 thr, 8x4 micro, prefetch-pipelined --------
template<bool GATHER, bool RELU>
__global__ __launch_bounds__(256) void gemm_kernel(
    const float* __restrict__ A, const float* __restrict__ Bm, float* __restrict__ C,
    int M, int N, int K, const float* __restrict__ bias,
    const int* __restrict__ tok, const float* __restrict__ emb)
{
    __shared__ float AsT[16][136];      // [k][m], transposed A tile
    __shared__ float Bs [16][68];
    __shared__ int   toks[128];
    const int t = threadIdx.x, tx = t & 15, ty = t >> 4;
    const int n0 = blockIdx.x << 6, m0 = blockIdx.y << 7;
    const int ar = t >> 1, ac8 = (t & 1) << 3;      // A loader: row, 8-col group
    const int bk = t >> 4, bn4 = (t & 15) << 2;     // B loader
    if (GATHER) { if (t < 128) toks[t] = tok[m0 + t]; __syncthreads(); }
    float acc[8][4];
#pragma unroll
    for (int i = 0; i < 8; i++)
#pragma unroll
        for (int j = 0; j < 4; j++) acc[i][j] = 0.f;
    const float* arow = GATHER ? (emb + (size_t)toks[ar] * K)
                               : (A   + (size_t)(m0 + ar) * K);
    float4 av0 = *(const float4*)(arow + ac8);
    float4 av1 = *(const float4*)(arow + ac8 + 4);
    float4 bv  = *(const float4*)(Bm + (size_t)bk * N + n0 + bn4);
    int k0 = 0;
    while (true) {
        __syncthreads();
        AsT[ac8+0][ar]=av0.x; AsT[ac8+1][ar]=av0.y;
        AsT[ac8+2][ar]=av0.z; AsT[ac8+3][ar]=av0.w;
        AsT[ac8+4][ar]=av1.x; AsT[ac8+5][ar]=av1.y;
        AsT[ac8+6][ar]=av1.z; AsT[ac8+7][ar]=av1.w;
        *(float4*)(&Bs[bk][bn4]) = bv;
        __syncthreads();
        k0 += 16;
        bool more = (k0 < K);
        if (more) {
            av0 = *(const float4*)(arow + k0 + ac8);
            av1 = *(const float4*)(arow + k0 + ac8 + 4);
            bv  = *(const float4*)(Bm + (size_t)(k0 + bk) * N + n0 + bn4);
        }
#pragma unroll
        for (int kk = 0; kk < 16; kk++) {
            float a[8], b[4];
            *(float4*)a     = *(const float4*)(&AsT[kk][ty << 3]);
            *(float4*)(a+4) = *(const float4*)(&AsT[kk][(ty << 3) + 4]);
            *(float4*)b     = *(const float4*)(&Bs [kk][tx << 2]);
#pragma unroll
            for (int i = 0; i < 8; i++)
#pragma unroll
                for (int j = 0; j < 4; j++) acc[i][j] = fmaf(a[i], b[j], acc[i][j]);
        }
        if (!more) break;
    }
    float bb[4];
    *(float4*)bb = *(const float4*)(bias + n0 + (tx << 2));
#pragma unroll
    for (int i = 0; i < 8; i++) {
        float4 ov;
        ov.x = acc[i][0]+bb[0]; ov.y = acc[i][1]+bb[1];
        ov.z = acc[i][2]+bb[2]; ov.w = acc[i][3]+bb[3];
        if (RELU) { ov.x=fmaxf(ov.x,0.f); ov.y=fmaxf(ov.y,0.f);
                    ov.z=fmaxf(ov.z,0.f); ov.w=fmaxf(ov.w,0.f); }
        *(float4*)(C + (size_t)(m0 + (ty << 3) + i) * N + n0 + (tx << 2)) = ov;
    }
}

// ---------------------------------------------------------------------------
// QLSTM recurrence, cluster version with writer-side DSMEM push exchange.
// 128 CTAs = 16 batches x 8 slices. W slice (128KB) lives in smem.
// Per step: smem dot, local cumprod, PUSH scanned slice to all 8 peers
// (double-buffered), ONE cluster.sync, local gate reads, state update.
// PE is fused into the h store.
// ---------------------------------------------------------------------------
#define LSTM_SMEM_FLOATS (32768 + 8*132 + 2*8*132 + 256 + 256 + 8)
__global__ __cluster_dims__(8,1,1) __launch_bounds__(256)
void lstm_kernel(const float* __restrict__ W, float* __restrict__ hseq)
{
    extern __shared__ float sm[];
    float* Wsm  = sm;                          // [256][128]
    float* red  = sm + 32768;                  // [8][132]
    float* allq = red + 8*132;                 // [2][8][132] push buffers
    float* hx   = allq + 2*8*132;              // [256]
    float* cx   = hx + 256;                    // [256]
    float* wtot = cx + 256;                    // [8]

    cg::cluster_group cluster = cg::this_cluster();
    const int rank = (int)cluster.block_rank();
    const int g    = rank >> 1, half = rank & 1;
    const int b    = blockIdx.x >> 3;
    const int t    = threadIdx.x;
    const int ks   = t >> 5, jc = t & 31;
    const int lane = t & 31, w = t >> 5;

    // preload W slice: rows k in [0,256), cols [g*256 + half*128, +128)
    const float* gW = W + g * 131072 + 65536 + half * 128;
    for (int i = t; i < 8192; i += 256) {
        int k = i >> 5, j4 = (i & 31) << 2;
        *(float4*)&Wsm[k * 128 + j4] = *(const float4*)(gW + (size_t)k * 256 + j4);
    }
    hx[t] = 0.f; cx[t] = 0.f;

    // fused positional encoding for the stored h (only rank 0 stores)
    float pediv = __expf((float)((t >> 1) << 1) * (-9.210340371976184f / 256.f));

    // peer allq pointers (push targets)
    float* paq[8];
#pragma unroll
    for (int r = 0; r < 8; r++)
        paq[r] = (float*)cluster.map_shared_rank((void*)allq, r);

    __syncthreads();
    cluster.sync();   // all peers' buffers valid before anyone pushes

    const float* zxp = g_zx + (size_t)b * 256 * 1024 + g * 256 + half * 128;

    for (int step = 0; step < 256; ++step) {
        const int par = step & 1;
        // ---- dot: z_partial over k = ks + 8*kk ----
        float a0=0.f, a1=0.f, a2=0.f, a3=0.f;
        const float* wp = Wsm + ks * 128 + (jc << 2);
#pragma unroll 8
        for (int kk = 0; kk < 32; ++kk) {
            float  hv = hx[(kk << 3) + ks];
            float4 wv = *(const float4*)wp;
            a0 = fmaf(hv, wv.x, a0); a1 = fmaf(hv, wv.y, a1);
            a2 = fmaf(hv, wv.z, a2); a3 = fmaf(hv, wv.w, a3);
            wp += 8 * 128;
        }
        *(float4*)&red[ks * 132 + (jc << 2)] = make_float4(a0, a1, a2, a3);
        __syncthreads();
        // ---- z, cos, local inclusive cumprod over this CTA's 128 cols ----
        float p = 0.f;
        if (t < 128) {
            float z = red[t] + red[132 + t] + red[264 + t] + red[396 + t]
                    + red[528 + t] + red[660 + t] + red[792 + t] + red[924 + t]
                    + zxp[(size_t)step * 1024 + t];
            p = __cosf(z);
#pragma unroll
            for (int off = 1; off < 32; off <<= 1) {
                float u = __shfl_up_sync(0xffffffffu, p, off);
                if (lane >= off) p *= u;
            }
            if (lane == 31) wtot[w] = p;
        }
        __syncthreads();
        if (t < 128) {
            float pre = 1.f;
            for (int ww = 0; ww < w; ++ww) pre *= wtot[ww];
            float sv = p * pre;
            const int dst = par * 1056 + rank * 132 + t;
#pragma unroll
            for (int r = 0; r < 8; r++) paq[r][dst] = sv;   // push to all peers
        }
        cluster.sync();
        // ---- gates from LOCAL allq + state update (replicated) ----
        {
            const int sh = t >> 7, off = t & 127;
            const float* aq = allq + par * 1056;
            float qg4[4];
#pragma unroll
            for (int gg = 0; gg < 4; gg++) {
                float v = aq[(gg * 2 + sh) * 132 + off];
                if (sh) v *= aq[(gg * 2) * 132 + 127];
                qg4[gg] = v;
            }
            float f  = sigm_f(qg4[0]);
            float ii = sigm_f(qg4[1]);
            float gg = tanh_f(qg4[2]);
            float oo = sigm_f(qg4[3]);
            float cn = f * cx[t] + ii * gg;
            cx[t] = cn;
            float hn = oo * tanh_f(cn);
            hx[t] = hn;
            if (rank == 0) {
                float ang = (float)step * pediv;
                float pe  = (t & 1) ? __cosf(ang) : __sinf(ang);
                hseq[((size_t)b * 256 + step) * 256 + t] = hn + pe;
            }
        }
        __syncthreads();
    }
}

// fused q/k/v qproj: one warp per row, reads h once, writes 3 outputs
__global__ void qproj3_kernel(const float* __restrict__ h, const float* __restrict__ th,
                              float* __restrict__ qo, float* __restrict__ ko,
                              float* __restrict__ vo) {
    const int w = threadIdx.x >> 5, lane = threadIdx.x & 31;
    const int row = blockIdx.x * 8 + w;
    const float* hr = h + (size_t)row * 256 + lane * 8;
    float4 h0 = *(const float4*)hr, h1 = *(const float4*)(hr + 4);
    float* outs[3] = {qo, ko, vo};
#pragma unroll
    for (int c = 0; c < 3; c++) {
        const float* tr = th + c * 256 + lane * 8;
        float4 t0 = *(const float4*)tr, t1 = *(const float4*)(tr + 4);
        float p[8], run;
        run  = __cosf(h0.x+t0.x); p[0]=run;  run *= __cosf(h0.y+t0.y); p[1]=run;
        run *= __cosf(h0.z+t0.z); p[2]=run;  run *= __cosf(h0.w+t0.w); p[3]=run;
        run *= __cosf(h1.x+t1.x); p[4]=run;  run *= __cosf(h1.y+t1.y); p[5]=run;
        run *= __cosf(h1.z+t1.z); p[6]=run;  run *= __cosf(h1.w+t1.w); p[7]=run;
        float incl = run;
#pragma unroll
        for (int off = 1; off < 32; off <<= 1) {
            float u = __shfl_up_sync(0xffffffffu, incl, off);
            if (lane >= off) incl *= u;
        }
        float ex = __shfl_up_sync(0xffffffffu, incl, 1);
        if (lane == 0) ex = 1.f;
        float* o = outs[c] + (size_t)row * 256 + lane * 8;
        *(float4*)o     = make_float4(ex*p[0], ex*p[1], ex*p[2], ex*p[3]);
        *(float4*)(o+4) = make_float4(ex*p[4], ex*p[5], ex*p[6], ex*p[7]);
    }
}

// fused attention: one CTA per (b,head); K and V^T staged in smem
__global__ __launch_bounds__(256) void attn_kernel(const float* __restrict__ Q,
    const float* __restrict__ K, const float* __restrict__ V, float* __restrict__ O)
{
    extern __shared__ float sm[];
    float* kh = sm;               // [256][36]
    float* vt = sm + 256 * 36;    // [32][260]
    float* ps = vt + 32 * 260;    // [8][256]
    float* qs = ps + 8 * 256;     // [8][32]
    const int b = blockIdx.x >> 3, hh = blockIdx.x & 7;
    const int t = threadIdx.x, w = t >> 5, lane = t & 31;
    const size_t base = ((size_t)b * 256) * 256 + hh * 32;
    for (int idx = t; idx < 8192; idx += 256) {
        int kr = idx >> 5, d = idx & 31;
        size_t go = base + (size_t)kr * 256 + d;
        kh[kr * 36 + d]  = K[go];
        vt[d * 260 + kr] = V[go];
    }
    __syncthreads();
    float* qsw = qs + w * 32;
    float* psw = ps + w * 256;
    for (int r = w; r < 256; r += 8) {
        qsw[lane] = Q[base + (size_t)r * 256 + lane];
        __syncwarp();
        float s[8];
#pragma unroll
        for (int c = 0; c < 8; c++) {
            const float* kr = kh + (c * 32 + lane) * 36;
            float acc = 0.f;
#pragma unroll
            for (int d4 = 0; d4 < 8; d4++) {
                float4 kv = *(const float4*)(kr + (d4 << 2));
                float4 qv = *(const float4*)(qsw + (d4 << 2));
                acc = fmaf(kv.x,qv.x,acc); acc = fmaf(kv.y,qv.y,acc);
                acc = fmaf(kv.z,qv.z,acc); acc = fmaf(kv.w,qv.w,acc);
            }
            s[c] = acc * 0.17677669529663689f;
        }
        float m = s[0];
#pragma unroll
        for (int c = 1; c < 8; c++) m = fmaxf(m, s[c]);
#pragma unroll
        for (int off = 16; off; off >>= 1) m = fmaxf(m, __shfl_xor_sync(0xffffffffu, m, off));
        float sum = 0.f;
#pragma unroll
        for (int c = 0; c < 8; c++) { s[c] = __expf(s[c] - m); sum += s[c]; }
#pragma unroll
        for (int off = 16; off; off >>= 1) sum += __shfl_xor_sync(0xffffffffu, sum, off);
#pragma unroll
        for (int c = 0; c < 8; c++) psw[c * 32 + lane] = s[c];
        __syncwarp();
        float acc = 0.f;
        const float* vr = vt + lane * 260;
#pragma unroll
        for (int k4 = 0; k4 < 64; k4++) {
            float4 pv = *(const float4*)(psw + (k4 << 2));
            float4 vv = *(const float4*)(vr  + (k4 << 2));
            acc = fmaf(pv.x,vv.x,acc); acc = fmaf(pv.y,vv.y,acc);
            acc = fmaf(pv.z,vv.z,acc); acc = fmaf(pv.w,vv.w,acc);
        }
        O[base + (size_t)r * 256 + lane] = acc / sum;
        __syncwarp();
    }
}

// residual add + LayerNorm; optionally fused qproj of the LN output
template<bool DOQ>
__global__ void resid_ln_kernel(float* __restrict__ h, const float* __restrict__ d,
                                const float* __restrict__ gw, const float* __restrict__ bw,
                                const float* __restrict__ th, float* __restrict__ qout) {
    const int row = blockIdx.x, j = threadIdx.x, w = j >> 5, lane = j & 31;
    __shared__ float ssum[8], ssq[8], wtot[8];
    size_t off = (size_t)row * 256 + j;
    float v = h[off] + d[off];
    float s = v, s2 = v * v;
#pragma unroll
    for (int o = 16; o; o >>= 1) {
        s  += __shfl_xor_sync(0xffffffffu, s, o);
        s2 += __shfl_xor_sync(0xffffffffu, s2, o);
    }
    if (lane == 0) { ssum[w] = s; ssq[w] = s2; }
    __syncthreads();
    if (j == 0) {
        float S = 0.f, S2 = 0.f;
        for (int i = 0; i < 8; i++) { S += ssum[i]; S2 += ssq[i]; }
        ssum[0] = S; ssq[0] = S2;
    }
    __syncthreads();
    float mean = ssum[0] * (1.f/256.f);
    float var  = ssq[0]  * (1.f/256.f) - mean * mean;
    float nv = (v - mean) * rsqrtf(var + 1e-5f) * gw[j] + bw[j];
    h[off] = nv;
    if (DOQ) {
        float p = __cosf(nv + th[j]);
#pragma unroll
        for (int o = 1; o < 32; o <<= 1) {
            float u = __shfl_up_sync(0xffffffffu, p, o);
            if (lane >= o) p *= u;
        }
        if (lane == 31) wtot[w] = p;
        __syncthreads();
        float pre = 1.f;
        for (int ww = 0; ww < w; ++ww) pre *= wtot[ww];
        qout[off] = p * pre;
    }
}

__global__ void pool_cls_kernel(const float* __restrict__ h, const float* __restrict__ Wc,
                                const float* __restrict__ bc, float* __restrict__ out) {
    __shared__ float pooled[256];
    const int b = blockIdx.x, e = threadIdx.x;
    float s = 0.f;
    for (int tt = 0; tt < 256; ++tt) s += h[((size_t)b * 256 + tt) * 256 + e];
    pooled[e] = s * (1.f/256.f);
    __syncthreads();
    if (e < 4) {
        float a = bc[e];
        for (int i = 0; i < 256; i++) a = fmaf(pooled[i], Wc[i * 4 + e], a);
        out[b * 4 + e] = a;
    }
}

extern "C" void kernel_launch(void* const* d_in, const int* in_sizes, int n_in,
                              void* d_out, int out_size)
{
    const int*   x      = (const int*)  d_in[0];
    const float* tokemb = (const float*)d_in[1];
    const float* lstmW  = (const float*)d_in[2];
    const float* lstmB  = (const float*)d_in[3];
    const float* lstmTh = (const float*)d_in[4];
    const float* ln1g   = (const float*)d_in[5];
    const float* ln1b   = (const float*)d_in[6];
    const float* ln2g   = (const float*)d_in[7];
    const float* ln2b   = (const float*)d_in[8];
    const float* qkvTh  = (const float*)d_in[9];
    const float* combW  = (const float*)d_in[10];
    const float* combB  = (const float*)d_in[11];
    const float* ffnTh  = (const float*)d_in[12];
    const float* lin1W  = (const float*)d_in[13];
    const float* lin1B  = (const float*)d_in[14];
    const float* lin2W  = (const float*)d_in[15];
    const float* lin2B  = (const float*)d_in[16];
    const float* clsW   = (const float*)d_in[17];
    const float* clsB   = (const float*)d_in[18];
    float* out = (float*)d_out;

    float *p_zx,*p_wxp,*p_bth,*p_h,*p_q,*p_k,*p_v,*p_at,*p_ffq,*p_t1,*p_t2;
    cudaGetSymbolAddress((void**)&p_zx,  g_zx);
    cudaGetSymbolAddress((void**)&p_wxp, g_wxp);
    cudaGetSymbolAddress((void**)&p_bth, g_bth);
    cudaGetSymbolAddress((void**)&p_h,   g_h);
    cudaGetSymbolAddress((void**)&p_q,   g_q);
    cudaGetSymbolAddress((void**)&p_k,   g_k);
    cudaGetSymbolAddress((void**)&p_v,   g_v);
    cudaGetSymbolAddress((void**)&p_at,  g_at);
    cudaGetSymbolAddress((void**)&p_ffq, g_ffq);
    cudaGetSymbolAddress((void**)&p_t1,  g_t1);
    cudaGetSymbolAddress((void**)&p_t2,  g_t2);

    cudaFuncSetAttribute(attn_kernel, cudaFuncAttributeMaxDynamicSharedMemorySize, 79360);
    cudaFuncSetAttribute(lstm_kernel, cudaFuncAttributeMaxDynamicSharedMemorySize,
                         LSTM_SMEM_FLOATS * 4);

    pack_kernel<<<1024, 256>>>(lstmW, lstmB, lstmTh);
    gemm_kernel<true, false><<<dim3(16, 32), 256>>>(
        nullptr, p_wxp, p_zx, ROWS, 1024, 256, p_bth, x, tokemb);
    lstm_kernel<<<128, 256, LSTM_SMEM_FLOATS * 4>>>(lstmW, p_h);

    for (int l = 0; l < 2; l++) {
        qproj3_kernel<<<ROWS/8, 256>>>(p_h, qkvTh + l*3*256, p_q, p_k, p_v);
        attn_kernel<<<Bb*8, 256, 79360>>>(p_q, p_k, p_v, p_at);
        gemm_kernel<false, false><<<dim3(4, 32), 256>>>(
            p_at, combW + l*256*256, p_t2, ROWS, 256, 256,
            combB + l*256, nullptr, nullptr);
        resid_ln_kernel<true><<<ROWS, 256>>>(p_h, p_t2, ln1g + l*256, ln1b + l*256,
                                             ffnTh + l*256, p_ffq);
        gemm_kernel<false, true><<<dim3(16, 32), 256>>>(
            p_ffq, lin1W + l*256*1024, p_t1, ROWS, 1024, 256,
            lin1B + l*1024, nullptr, nullptr);
        gemm_kernel<false, false><<<dim3(4, 32), 256>>>(
            p_t1, lin2W + l*1024*256, p_t2, ROWS, 256, 1024,
            lin2B + l*256, nullptr, nullptr);
        resid_ln_kernel<false><<<ROWS, 256>>>(p_h, p_t2, ln2g + l*256, ln2b + l*256,
                                              nullptr, nullptr);
    }
    pool_cls_kernel<<<Bb, 256>>>(p_h, clsW, clsB, out);
}